// round 10
// baseline (speedup 1.0000x reference)
#include <cuda_runtime.h>
#include <cuda_bf16.h>
#include <cuda_fp16.h>
#include <mma.h>
#include <math_constants.h>

using namespace nvcuda;

// Problem constants
#define N_NODES   50000
#define N_EDGES   800000
#define IN_FEATS  256
#define EDGE_FEATS 64
#define NUM_HEADS 4
#define OUT_FEATS 32
#define HF        128           // NUM_HEADS*OUT_FEATS
#define QCOLS     256           // NUM_HEADS*EDGE_FEATS
#define NCAT      384           // HF + QCOLS

#define SCAN_BLK  512
#define NB_SCAN   ((N_NODES + SCAN_BLK - 1) / SCAN_BLK)   // 98

#define GM_BM 128
#define GM_BK 32

// Scratch (static device globals; no allocation allowed)
__device__ __half g_wcat[IN_FEATS * NCAT];     // [W_node | W_node@Wbig*scale] fp16
__device__ __half g_hh[N_NODES * HF];          // projected node feats fp16
__device__ __half g_qh[N_NODES * QCOLS];       // q[n,h,k] fp16 (scale baked in)
__device__ int    g_cnt[N_NODES];
__device__ int    g_off[N_NODES + 1];
__device__ int    g_cur[N_NODES];
__device__ int2   g_es[N_EDGES];               // (eid, src) grouped by dst
__device__ int    g_part[NB_SCAN];
__device__ int    g_partx[NB_SCAN];

// ---------------------------------------------------------------------------
// Wcat precompute (also zeroes g_cnt: 256 blocks x 384 thr = 98304 >= 50000).
// ---------------------------------------------------------------------------
__global__ __launch_bounds__(NCAT) void wcat_kernel(
    const float* __restrict__ Wn, const float* __restrict__ We) {
    __shared__ float We_s[EDGE_FEATS * HF];   // 32KB
    __shared__ float wn_row[HF];

    const int c_in = blockIdx.x;
    const int j = threadIdx.x;

    const int zi = blockIdx.x * NCAT + j;
    if (zi < N_NODES) g_cnt[zi] = 0;

    for (int i = j; i < EDGE_FEATS * HF; i += NCAT) We_s[i] = We[i];
    if (j < HF) wn_row[j] = Wn[(size_t)c_in * HF + j];
    __syncthreads();

    float out;
    if (j < HF) {
        out = wn_row[j];
    } else {
        const int jj = j - HF;
        const int h = jj >> 6;
        const int k = jj & 63;
        float acc = 0.0f;
#pragma unroll
        for (int f = 0; f < OUT_FEATS; f++)
            acc += wn_row[h * OUT_FEATS + f] * We_s[k * HF + h * OUT_FEATS + f];
        out = acc * 0.17677669529663687f;   // 1/sqrt(32)
    }
    g_wcat[(size_t)c_in * NCAT + j] = __float2half_rn(out);
}

// ---------------------------------------------------------------------------
// Single fused GEMM: [h | q] = A[50000,256] @ Wcat[256,384], wmma fp16/fp32.
// Double-buffered smem mainloop: register-staged LDGs for stage k+1 issued
// before the MMAs on stage k; STS to alternate buffer; one sync per k-step.
// grid (3 n-tiles, 391 m-tiles) so the 3 n-tiles of an m-tile share A in L2.
// ---------------------------------------------------------------------------
__global__ __launch_bounds__(256) void gemm_cat_kernel(const float* __restrict__ A) {
    __shared__ __half As[2][GM_BM][GM_BK + 8];   // 2 x 128x40 halves (20KB)
    __shared__ __half Ws[2][GM_BK][128 + 8];     // 2 x 32x136 halves (17.4KB)
    __shared__ float  patch[8][16 * 16];         // per-warp staging (8KB)

    const int tid  = threadIdx.x;
    const int warp = tid >> 5;
    const int lane = tid & 31;
    const int wm   = warp >> 1;     // 0..3
    const int wn   = warp & 1;      // 0..1
    const int m0   = blockIdx.y * GM_BM;
    const int nbase = blockIdx.x * 128;

    // per-thread tile coords for loads
    const int ar = tid >> 3;              // A rows: 4 rows per thread (stride 32... see below)
    const int ac = (tid & 7) * 4;
    const int wr = tid >> 4;              // W: 2 uint4 per thread
    const int wc = (tid & 15) * 8;

    wmma::fragment<wmma::accumulator, 16, 16, 16, float> c[2][4];
#pragma unroll
    for (int i = 0; i < 2; i++)
#pragma unroll
        for (int j = 0; j < 4; j++) wmma::fill_fragment(c[i][j], 0.0f);

    float4 areg[4];
    uint4  wreg[2];

    // --- load stage 0 into registers ---
#pragma unroll
    for (int i = 0; i < 4; i++) {
        int gr = m0 + ar + i * 32;
        areg[i] = make_float4(0.f, 0.f, 0.f, 0.f);
        if (gr < N_NODES) areg[i] = *(const float4*)&A[(size_t)gr * IN_FEATS + ac];
    }
#pragma unroll
    for (int i = 0; i < 2; i++)
        wreg[i] = *(const uint4*)&g_wcat[(size_t)(wr + i * 16) * NCAT + nbase + wc];

    // --- store stage 0 into buffer 0 ---
#pragma unroll
    for (int i = 0; i < 4; i++) {
        As[0][ar + i * 32][ac + 0] = __float2half_rn(areg[i].x);
        As[0][ar + i * 32][ac + 1] = __float2half_rn(areg[i].y);
        As[0][ar + i * 32][ac + 2] = __float2half_rn(areg[i].z);
        As[0][ar + i * 32][ac + 3] = __float2half_rn(areg[i].w);
    }
#pragma unroll
    for (int i = 0; i < 2; i++)
        *(uint4*)&Ws[0][wr + i * 16][wc] = wreg[i];
    __syncthreads();

    int buf = 0;
#pragma unroll
    for (int k0 = 0; k0 < IN_FEATS; k0 += GM_BK) {
        const bool has_next = (k0 + GM_BK < IN_FEATS);

        // issue next-stage global loads first (latency hidden by MMAs below)
        if (has_next) {
            const int kn = k0 + GM_BK;
#pragma unroll
            for (int i = 0; i < 4; i++) {
                int gr = m0 + ar + i * 32;
                areg[i] = make_float4(0.f, 0.f, 0.f, 0.f);
                if (gr < N_NODES) areg[i] = *(const float4*)&A[(size_t)gr * IN_FEATS + kn + ac];
            }
#pragma unroll
            for (int i = 0; i < 2; i++)
                wreg[i] = *(const uint4*)&g_wcat[(size_t)(kn + wr + i * 16) * NCAT + nbase + wc];
        }

        // MMAs on current buffer
#pragma unroll
        for (int kk = 0; kk < GM_BK; kk += 16) {
            wmma::fragment<wmma::matrix_a, 16, 16, 16, __half, wmma::row_major> a[2];
            wmma::fragment<wmma::matrix_b, 16, 16, 16, __half, wmma::row_major> b[4];
#pragma unroll
            for (int i = 0; i < 2; i++)
                wmma::load_matrix_sync(a[i], &As[buf][wm * 32 + i * 16][kk], GM_BK + 8);
#pragma unroll
            for (int j = 0; j < 4; j++)
                wmma::load_matrix_sync(b[j], &Ws[buf][kk][wn * 64 + j * 16], 128 + 8);
#pragma unroll
            for (int i = 0; i < 2; i++)
#pragma unroll
                for (int j = 0; j < 4; j++)
                    wmma::mma_sync(c[i][j], a[i], b[j], c[i][j]);
        }

        // store next stage into alternate buffer
        if (has_next) {
            const int nb = buf ^ 1;
#pragma unroll
            for (int i = 0; i < 4; i++) {
                As[nb][ar + i * 32][ac + 0] = __float2half_rn(areg[i].x);
                As[nb][ar + i * 32][ac + 1] = __float2half_rn(areg[i].y);
                As[nb][ar + i * 32][ac + 2] = __float2half_rn(areg[i].z);
                As[nb][ar + i * 32][ac + 3] = __float2half_rn(areg[i].w);
            }
#pragma unroll
            for (int i = 0; i < 2; i++)
                *(uint4*)&Ws[nb][wr + i * 16][wc] = wreg[i];
            __syncthreads();
            buf = nb;
        }
    }

    // Epilogue: fragment -> smem patch -> fp16 global (g_hh or g_qh).
    __syncthreads();
    const int prow = lane >> 1;
    const int pcol = (lane & 1) * 8;
#pragma unroll
    for (int i = 0; i < 2; i++) {
#pragma unroll
        for (int j = 0; j < 4; j++) {
            wmma::store_matrix_sync(patch[warp], c[i][j], 16, wmma::mem_row_major);
            __syncwarp();
            const int n = m0 + wm * 32 + i * 16 + prow;
            if (n < N_NODES) {
                const float* pr = patch[warp] + prow * 16 + pcol;
                union { uint4 u; __half2 h2[4]; } pack;
                pack.h2[0] = __floats2half2_rn(pr[0], pr[1]);
                pack.h2[1] = __floats2half2_rn(pr[2], pr[3]);
                pack.h2[2] = __floats2half2_rn(pr[4], pr[5]);
                pack.h2[3] = __floats2half2_rn(pr[6], pr[7]);
                const int C = nbase + wn * 64 + j * 16 + pcol;   // 0..383
                if (C < HF) {
                    *(uint4*)&g_hh[(size_t)n * HF + C] = pack.u;
                } else {
                    *(uint4*)&g_qh[(size_t)n * QCOLS + (C - HF)] = pack.u;
                }
            }
            __syncwarp();
        }
    }
}

// ---------------------------------------------------------------------------
// CSR build: histogram -> scan (3 kernels) -> scatter (packed int2)
// ---------------------------------------------------------------------------
__global__ void hist_kernel(const int* __restrict__ dst) {
    int e = blockIdx.x * blockDim.x + threadIdx.x;
    if (e < N_EDGES) atomicAdd(&g_cnt[dst[e]], 1);
}

__global__ __launch_bounds__(SCAN_BLK) void scan1_kernel() {
    __shared__ int sm[SCAN_BLK];
    int t = threadIdx.x;
    int i = blockIdx.x * SCAN_BLK + t;
    sm[t] = (i < N_NODES) ? g_cnt[i] : 0;
    __syncthreads();
    for (int off = SCAN_BLK / 2; off > 0; off >>= 1) {
        if (t < off) sm[t] += sm[t + off];
        __syncthreads();
    }
    if (t == 0) g_part[blockIdx.x] = sm[0];
}

__global__ __launch_bounds__(128) void scan2_kernel() {
    __shared__ int sm[2][128];
    int t = threadIdx.x;
    int v = (t < NB_SCAN) ? g_part[t] : 0;
    int pi = 0;
    sm[0][t] = v;
    __syncthreads();
#pragma unroll
    for (int off = 1; off < 128; off <<= 1) {
        int add = (t >= off) ? sm[pi][t - off] : 0;
        sm[pi ^ 1][t] = sm[pi][t] + add;
        pi ^= 1;
        __syncthreads();
    }
    if (t < NB_SCAN) g_partx[t] = sm[pi][t] - v;   // exclusive
}

__global__ __launch_bounds__(SCAN_BLK) void scan3_kernel() {
    __shared__ int sm[2][SCAN_BLK];
    int t = threadIdx.x;
    int i = blockIdx.x * SCAN_BLK + t;
    int v = (i < N_NODES) ? g_cnt[i] : 0;
    int pi = 0;
    sm[0][t] = v;
    __syncthreads();
#pragma unroll
    for (int off = 1; off < SCAN_BLK; off <<= 1) {
        int add = (t >= off) ? sm[pi][t - off] : 0;
        sm[pi ^ 1][t] = sm[pi][t] + add;
        pi ^= 1;
        __syncthreads();
    }
    if (i < N_NODES) {
        int excl = g_partx[blockIdx.x] + sm[pi][t] - v;
        g_off[i] = excl;
        g_cur[i] = excl;
    }
    if (blockIdx.x == 0 && t == 0) g_off[N_NODES] = N_EDGES;
}

__global__ void scatter_kernel(const int* __restrict__ src, const int* __restrict__ dst) {
    int e = blockIdx.x * blockDim.x + threadIdx.x;
    if (e < N_EDGES) {
        int pos = atomicAdd(&g_cur[dst[e]], 1);
        g_es[pos] = make_int2(e, src[e]);
    }
}

// ---------------------------------------------------------------------------
// Fused: warp per dst node, NO max subtraction (softmax shift-invariant,
// scores O(1)). lane l: head h=l>>3, k-chunk k0=(l&7)*8.
// Prefetch distance 2 on the (eid,src) chain to decouple the dependent-load
// chain (es -> ef/q gathers) across iterations.
// ---------------------------------------------------------------------------
__global__ __launch_bounds__(256) void fused_kernel(
    const float* __restrict__ ef, float* __restrict__ out) {
    const int d = (blockIdx.x * 256 + threadIdx.x) >> 5;
    if (d >= N_NODES) return;
    const int lane = threadIdx.x & 31;
    const int h  = lane >> 3;
    const int k0 = (lane & 7) * 8;

    const int beg = __ldg(&g_off[d]);
    const int end = __ldg(&g_off[d + 1]);

    float den = 0.0f;
    float4 acc = make_float4(0.f, 0.f, 0.f, 0.f);

    if (beg < end) {
        const int last = end - 1;
        int2 e0 = __ldg(&g_es[beg]);
        int2 e1 = (beg < last) ? __ldg(&g_es[beg + 1]) : e0;

#pragma unroll 2
        for (int j = beg; j < end; j++) {
            const int eid_c = e0.x;
            const int s_c   = e0.y;
            e0 = e1;
            const int jn2 = (j + 2 < end) ? j + 2 : last;   // clamped
            e1 = __ldg(&g_es[jn2]);

            const float4 ef0 = *(const float4*)(ef + (size_t)eid_c * EDGE_FEATS + k0);
            const float4 ef1 = *(const float4*)(ef + (size_t)eid_c * EDGE_FEATS + k0 + 4);

            const uint4 qv = *(const uint4*)(g_qh + (size_t)s_c * QCOLS + h * EDGE_FEATS + k0);
            const float2 q0 = __half22float2(*(const __half2*)&qv.x);
            const float2 q1 = __half22float2(*(((const __half2*)&qv.x) + 1));
            const float2 q2 = __half22float2(*(const __half2*)&qv.z);
            const float2 q3 = __half22float2(*(((const __half2*)&qv.z) + 1));

            float p = ef0.x * q0.x + ef0.y * q0.y + ef0.z * q1.x + ef0.w * q1.y
                    + ef1.x * q2.x + ef1.y * q2.y + ef1.z * q3.x + ef1.w * q3.y;
            p += __shfl_xor_sync(0xffffffffu, p, 1);
            p += __shfl_xor_sync(0xffffffffu, p, 2);
            p += __shfl_xor_sync(0xffffffffu, p, 4);

            const float sc = (p > 0.0f) ? p : 0.01f * p;   // leaky relu
            const float w  = __expf(sc);

            const uint2 hvu = *(const uint2*)(g_hh + (size_t)s_c * HF + lane * 4);
            const float2 h01 = __half22float2(*(const __half2*)&hvu.x);
            const float2 h23 = __half22float2(*(const __half2*)&hvu.y);

            den   += w;
            acc.x += w * h01.x;
            acc.y += w * h01.y;
            acc.z += w * h23.x;
            acc.w += w * h23.y;
        }
    }

    const float inv = (den > 0.0f) ? __frcp_rn(den) : 0.0f;
    float4 o = make_float4(acc.x * inv, acc.y * inv, acc.z * inv, acc.w * inv);
    *(float4*)(out + (size_t)d * HF + lane * 4) = o;
}

// ---------------------------------------------------------------------------
extern "C" void kernel_launch(void* const* d_in, const int* in_sizes, int n_in,
                              void* d_out, int out_size) {
    const float* node_feat = (const float*)d_in[0];
    const float* edge_feat = (const float*)d_in[1];
    const int*   src       = (const int*)d_in[2];
    const int*   dst       = (const int*)d_in[3];
    const float* W_node    = (const float*)d_in[4];
    const float* W_edge    = (const float*)d_in[5];
    float* out = (float*)d_out;

    wcat_kernel<<<IN_FEATS, NCAT>>>(W_node, W_edge);   // also zeroes g_cnt
    dim3 ggrid(3, (N_NODES + GM_BM - 1) / GM_BM);
    gemm_cat_kernel<<<ggrid, 256>>>(node_feat);
    hist_kernel<<<(N_EDGES + 255) / 256, 256>>>(dst);
    scan1_kernel<<<NB_SCAN, SCAN_BLK>>>();
    scan2_kernel<<<1, 128>>>();
    scan3_kernel<<<NB_SCAN, SCAN_BLK>>>();
    scatter_kernel<<<(N_EDGES + 255) / 256, 256>>>(src, dst);
    fused_kernel<<<(N_NODES * 32 + 255) / 256, 256>>>(edge_feat, out);
}

// round 11
// speedup vs baseline: 1.0112x; 1.0112x over previous
#include <cuda_runtime.h>
#include <cuda_bf16.h>
#include <cuda_fp16.h>
#include <mma.h>
#include <math_constants.h>

using namespace nvcuda;

// Problem constants
#define N_NODES   50000
#define N_EDGES   800000
#define IN_FEATS  256
#define EDGE_FEATS 64
#define NUM_HEADS 4
#define OUT_FEATS 32
#define HF        128           // NUM_HEADS*OUT_FEATS
#define QCOLS     256           // NUM_HEADS*EDGE_FEATS
#define NCAT      384           // HF + QCOLS

#define SCAN_BLK  512
#define NB_SCAN   ((N_NODES + SCAN_BLK - 1) / SCAN_BLK)   // 98

#define GM_BM 128
#define GM_BK 32

// Scratch (static device globals; no allocation allowed)
__device__ __half g_wcat[IN_FEATS * NCAT];     // [W_node | W_node@Wbig*scale] fp16
__device__ __half g_hh[N_NODES * HF];          // projected node feats fp16
__device__ __half g_qh[N_NODES * QCOLS];       // q[n,h,k] fp16 (scale baked in)
__device__ int    g_cnt[N_NODES];
__device__ int    g_off[N_NODES + 1];
__device__ int    g_cur[N_NODES];
__device__ int2   g_es[N_EDGES];               // (eid, src) grouped by dst
__device__ int    g_part[NB_SCAN];
__device__ int    g_partx[NB_SCAN];

// ---------------------------------------------------------------------------
__global__ void zero_cnt_kernel() {
    int i = blockIdx.x * blockDim.x + threadIdx.x;
    if (i < N_NODES) g_cnt[i] = 0;
}

// ---------------------------------------------------------------------------
// Wcat precompute.
//   j <  128: Wcat = W_node[c_in, j]
//   j >= 128: jj=j-128, h=jj>>6, k=jj&63:
//             Wcat = (1/sqrt32) * sum_f W_node[c_in, h*32+f] * We[k, h*32+f]
// ---------------------------------------------------------------------------
__global__ __launch_bounds__(NCAT) void wcat_kernel(
    const float* __restrict__ Wn, const float* __restrict__ We) {
    __shared__ float We_s[EDGE_FEATS * HF];   // 32KB
    __shared__ float wn_row[HF];

    const int c_in = blockIdx.x;
    const int j = threadIdx.x;

    for (int i = j; i < EDGE_FEATS * HF; i += NCAT) We_s[i] = We[i];
    if (j < HF) wn_row[j] = Wn[(size_t)c_in * HF + j];
    __syncthreads();

    float out;
    if (j < HF) {
        out = wn_row[j];
    } else {
        const int jj = j - HF;
        const int h = jj >> 6;
        const int k = jj & 63;
        float acc = 0.0f;
#pragma unroll
        for (int f = 0; f < OUT_FEATS; f++)
            acc += wn_row[h * OUT_FEATS + f] * We_s[k * HF + h * OUT_FEATS + f];
        out = acc * 0.17677669529663687f;   // 1/sqrt(32)
    }
    g_wcat[(size_t)c_in * NCAT + j] = __float2half_rn(out);
}

// ---------------------------------------------------------------------------
// Single fused GEMM: [h | q] = A[50000,256] @ Wcat[256,384], wmma fp16/fp32.
// Double-buffered smem mainloop; grid (3 n-tiles, 391 m-tiles) for A L2 reuse.
// ---------------------------------------------------------------------------
__global__ __launch_bounds__(256) void gemm_cat_kernel(const float* __restrict__ A) {
    __shared__ __half As[2][GM_BM][GM_BK + 8];
    __shared__ __half Ws[2][GM_BK][128 + 8];
    __shared__ float  patch[8][16 * 16];

    const int tid  = threadIdx.x;
    const int warp = tid >> 5;
    const int lane = tid & 31;
    const int wm   = warp >> 1;
    const int wn   = warp & 1;
    const int m0   = blockIdx.y * GM_BM;
    const int nbase = blockIdx.x * 128;

    const int ar = tid >> 3;
    const int ac = (tid & 7) * 4;
    const int wr = tid >> 4;
    const int wc = (tid & 15) * 8;

    wmma::fragment<wmma::accumulator, 16, 16, 16, float> c[2][4];
#pragma unroll
    for (int i = 0; i < 2; i++)
#pragma unroll
        for (int j = 0; j < 4; j++) wmma::fill_fragment(c[i][j], 0.0f);

    float4 areg[4];
    uint4  wreg[2];

#pragma unroll
    for (int i = 0; i < 4; i++) {
        int gr = m0 + ar + i * 32;
        areg[i] = make_float4(0.f, 0.f, 0.f, 0.f);
        if (gr < N_NODES) areg[i] = *(const float4*)&A[(size_t)gr * IN_FEATS + ac];
    }
#pragma unroll
    for (int i = 0; i < 2; i++)
        wreg[i] = *(const uint4*)&g_wcat[(size_t)(wr + i * 16) * NCAT + nbase + wc];

#pragma unroll
    for (int i = 0; i < 4; i++) {
        As[0][ar + i * 32][ac + 0] = __float2half_rn(areg[i].x);
        As[0][ar + i * 32][ac + 1] = __float2half_rn(areg[i].y);
        As[0][ar + i * 32][ac + 2] = __float2half_rn(areg[i].z);
        As[0][ar + i * 32][ac + 3] = __float2half_rn(areg[i].w);
    }
#pragma unroll
    for (int i = 0; i < 2; i++)
        *(uint4*)&Ws[0][wr + i * 16][wc] = wreg[i];
    __syncthreads();

    int buf = 0;
#pragma unroll
    for (int k0 = 0; k0 < IN_FEATS; k0 += GM_BK) {
        const bool has_next = (k0 + GM_BK < IN_FEATS);

        if (has_next) {
            const int kn = k0 + GM_BK;
#pragma unroll
            for (int i = 0; i < 4; i++) {
                int gr = m0 + ar + i * 32;
                areg[i] = make_float4(0.f, 0.f, 0.f, 0.f);
                if (gr < N_NODES) areg[i] = *(const float4*)&A[(size_t)gr * IN_FEATS + kn + ac];
            }
#pragma unroll
            for (int i = 0; i < 2; i++)
                wreg[i] = *(const uint4*)&g_wcat[(size_t)(kn + wr + i * 16) * NCAT + nbase + wc];
        }

#pragma unroll
        for (int kk = 0; kk < GM_BK; kk += 16) {
            wmma::fragment<wmma::matrix_a, 16, 16, 16, __half, wmma::row_major> a[2];
            wmma::fragment<wmma::matrix_b, 16, 16, 16, __half, wmma::row_major> b[4];
#pragma unroll
            for (int i = 0; i < 2; i++)
                wmma::load_matrix_sync(a[i], &As[buf][wm * 32 + i * 16][kk], GM_BK + 8);
#pragma unroll
            for (int j = 0; j < 4; j++)
                wmma::load_matrix_sync(b[j], &Ws[buf][kk][wn * 64 + j * 16], 128 + 8);
#pragma unroll
            for (int i = 0; i < 2; i++)
#pragma unroll
                for (int j = 0; j < 4; j++)
                    wmma::mma_sync(c[i][j], a[i], b[j], c[i][j]);
        }

        if (has_next) {
            const int nb = buf ^ 1;
#pragma unroll
            for (int i = 0; i < 4; i++) {
                As[nb][ar + i * 32][ac + 0] = __float2half_rn(areg[i].x);
                As[nb][ar + i * 32][ac + 1] = __float2half_rn(areg[i].y);
                As[nb][ar + i * 32][ac + 2] = __float2half_rn(areg[i].z);
                As[nb][ar + i * 32][ac + 3] = __float2half_rn(areg[i].w);
            }
#pragma unroll
            for (int i = 0; i < 2; i++)
                *(uint4*)&Ws[nb][wr + i * 16][wc] = wreg[i];
            __syncthreads();
            buf = nb;
        }
    }

    __syncthreads();
    const int prow = lane >> 1;
    const int pcol = (lane & 1) * 8;
#pragma unroll
    for (int i = 0; i < 2; i++) {
#pragma unroll
        for (int j = 0; j < 4; j++) {
            wmma::store_matrix_sync(patch[warp], c[i][j], 16, wmma::mem_row_major);
            __syncwarp();
            const int n = m0 + wm * 32 + i * 16 + prow;
            if (n < N_NODES) {
                const float* pr = patch[warp] + prow * 16 + pcol;
                union { uint4 u; __half2 h2[4]; } pack;
                pack.h2[0] = __floats2half2_rn(pr[0], pr[1]);
                pack.h2[1] = __floats2half2_rn(pr[2], pr[3]);
                pack.h2[2] = __floats2half2_rn(pr[4], pr[5]);
                pack.h2[3] = __floats2half2_rn(pr[6], pr[7]);
                const int C = nbase + wn * 64 + j * 16 + pcol;
                if (C < HF) {
                    *(uint4*)&g_hh[(size_t)n * HF + C] = pack.u;
                } else {
                    *(uint4*)&g_qh[(size_t)n * QCOLS + (C - HF)] = pack.u;
                }
            }
            __syncwarp();
        }
    }
}

// ---------------------------------------------------------------------------
// CSR build: histogram -> scan (3 kernels) -> scatter (packed int2)
// ---------------------------------------------------------------------------
__global__ void hist_kernel(const int* __restrict__ dst) {
    int e = blockIdx.x * blockDim.x + threadIdx.x;
    if (e < N_EDGES) atomicAdd(&g_cnt[dst[e]], 1);
}

__global__ __launch_bounds__(SCAN_BLK) void scan1_kernel() {
    __shared__ int sm[SCAN_BLK];
    int t = threadIdx.x;
    int i = blockIdx.x * SCAN_BLK + t;
    sm[t] = (i < N_NODES) ? g_cnt[i] : 0;
    __syncthreads();
    for (int off = SCAN_BLK / 2; off > 0; off >>= 1) {
        if (t < off) sm[t] += sm[t + off];
        __syncthreads();
    }
    if (t == 0) g_part[blockIdx.x] = sm[0];
}

__global__ __launch_bounds__(128) void scan2_kernel() {
    __shared__ int sm[2][128];
    int t = threadIdx.x;
    int v = (t < NB_SCAN) ? g_part[t] : 0;
    int pi = 0;
    sm[0][t] = v;
    __syncthreads();
#pragma unroll
    for (int off = 1; off < 128; off <<= 1) {
        int add = (t >= off) ? sm[pi][t - off] : 0;
        sm[pi ^ 1][t] = sm[pi][t] + add;
        pi ^= 1;
        __syncthreads();
    }
    if (t < NB_SCAN) g_partx[t] = sm[pi][t] - v;   // exclusive
}

__global__ __launch_bounds__(SCAN_BLK) void scan3_kernel() {
    __shared__ int sm[2][SCAN_BLK];
    int t = threadIdx.x;
    int i = blockIdx.x * SCAN_BLK + t;
    int v = (i < N_NODES) ? g_cnt[i] : 0;
    int pi = 0;
    sm[0][t] = v;
    __syncthreads();
#pragma unroll
    for (int off = 1; off < SCAN_BLK; off <<= 1) {
        int add = (t >= off) ? sm[pi][t - off] : 0;
        sm[pi ^ 1][t] = sm[pi][t] + add;
        pi ^= 1;
        __syncthreads();
    }
    if (i < N_NODES) {
        int excl = g_partx[blockIdx.x] + sm[pi][t] - v;
        g_off[i] = excl;
        g_cur[i] = excl;
    }
    if (blockIdx.x == 0 && t == 0) g_off[N_NODES] = N_EDGES;
}

__global__ void scatter_kernel(const int* __restrict__ src, const int* __restrict__ dst) {
    int e = blockIdx.x * blockDim.x + threadIdx.x;
    if (e < N_EDGES) {
        int pos = atomicAdd(&g_cur[dst[e]], 1);
        g_es[pos] = make_int2(e, src[e]);
    }
}

// ---------------------------------------------------------------------------
// Fused: warp per dst node, NO max subtraction. lane l: head h=l>>3,
// k-chunk k0=(l&7)*8. Prefetch distance 2 on the (eid,src) chain.
// ---------------------------------------------------------------------------
__global__ __launch_bounds__(256) void fused_kernel(
    const float* __restrict__ ef, float* __restrict__ out) {
    const int d = (blockIdx.x * 256 + threadIdx.x) >> 5;
    if (d >= N_NODES) return;
    const int lane = threadIdx.x & 31;
    const int h  = lane >> 3;
    const int k0 = (lane & 7) * 8;

    const int beg = __ldg(&g_off[d]);
    const int end = __ldg(&g_off[d + 1]);

    float den = 0.0f;
    float4 acc = make_float4(0.f, 0.f, 0.f, 0.f);

    if (beg < end) {
        const int last = end - 1;
        int2 e0 = __ldg(&g_es[beg]);
        int2 e1 = (beg < last) ? __ldg(&g_es[beg + 1]) : e0;

#pragma unroll 2
        for (int j = beg; j < end; j++) {
            const int eid_c = e0.x;
            const int s_c   = e0.y;
            e0 = e1;
            const int jn2 = (j + 2 < end) ? j + 2 : last;
            e1 = __ldg(&g_es[jn2]);

            const float4 ef0 = *(const float4*)(ef + (size_t)eid_c * EDGE_FEATS + k0);
            const float4 ef1 = *(const float4*)(ef + (size_t)eid_c * EDGE_FEATS + k0 + 4);

            const uint4 qv = *(const uint4*)(g_qh + (size_t)s_c * QCOLS + h * EDGE_FEATS + k0);
            const float2 q0 = __half22float2(*(const __half2*)&qv.x);
            const float2 q1 = __half22float2(*(((const __half2*)&qv.x) + 1));
            const float2 q2 = __half22float2(*(const __half2*)&qv.z);
            const float2 q3 = __half22float2(*(((const __half2*)&qv.z) + 1));

            float p = ef0.x * q0.x + ef0.y * q0.y + ef0.z * q1.x + ef0.w * q1.y
                    + ef1.x * q2.x + ef1.y * q2.y + ef1.z * q3.x + ef1.w * q3.y;
            p += __shfl_xor_sync(0xffffffffu, p, 1);
            p += __shfl_xor_sync(0xffffffffu, p, 2);
            p += __shfl_xor_sync(0xffffffffu, p, 4);

            const float sc = (p > 0.0f) ? p : 0.01f * p;   // leaky relu
            const float w  = __expf(sc);

            const uint2 hvu = *(const uint2*)(g_hh + (size_t)s_c * HF + lane * 4);
            const float2 h01 = __half22float2(*(const __half2*)&hvu.x);
            const float2 h23 = __half22float2(*(const __half2*)&hvu.y);

            den   += w;
            acc.x += w * h01.x;
            acc.y += w * h01.y;
            acc.z += w * h23.x;
            acc.w += w * h23.y;
        }
    }

    const float inv = (den > 0.0f) ? __frcp_rn(den) : 0.0f;
    float4 o = make_float4(acc.x * inv, acc.y * inv, acc.z * inv, acc.w * inv);
    *(float4*)(out + (size_t)d * HF + lane * 4) = o;
}

// ---------------------------------------------------------------------------
// Two independent branches forked off the capture stream:
//   A (default): wcat -> gemm_cat
//   B (s2):      zero -> hist -> scan1/2/3 -> scatter
// joined before fused. Stream/events lazily created on the first call
// (outside capture); the fork/join event pattern is graph-capturable.
// ---------------------------------------------------------------------------
extern "C" void kernel_launch(void* const* d_in, const int* in_sizes, int n_in,
                              void* d_out, int out_size) {
    const float* node_feat = (const float*)d_in[0];
    const float* edge_feat = (const float*)d_in[1];
    const int*   src       = (const int*)d_in[2];
    const int*   dst       = (const int*)d_in[3];
    const float* W_node    = (const float*)d_in[4];
    const float* W_edge    = (const float*)d_in[5];
    float* out = (float*)d_out;

    static cudaStream_t s2 = nullptr;
    static cudaEvent_t evFork = nullptr, evJoin = nullptr;
    if (s2 == nullptr) {
        cudaStreamCreateWithFlags(&s2, cudaStreamNonBlocking);
        cudaEventCreateWithFlags(&evFork, cudaEventDisableTiming);
        cudaEventCreateWithFlags(&evJoin, cudaEventDisableTiming);
    }

    // fork
    cudaEventRecord(evFork, 0);
    cudaStreamWaitEvent(s2, evFork, 0);

    // branch B: CSR build on s2
    zero_cnt_kernel<<<(N_NODES + 255) / 256, 256, 0, s2>>>();
    hist_kernel<<<(N_EDGES + 255) / 256, 256, 0, s2>>>(dst);
    scan1_kernel<<<NB_SCAN, SCAN_BLK, 0, s2>>>();
    scan2_kernel<<<1, 128, 0, s2>>>();
    scan3_kernel<<<NB_SCAN, SCAN_BLK, 0, s2>>>();
    scatter_kernel<<<(N_EDGES + 255) / 256, 256, 0, s2>>>(src, dst);
    cudaEventRecord(evJoin, s2);

    // branch A: projection GEMM on default stream
    wcat_kernel<<<IN_FEATS, NCAT>>>(W_node, W_edge);
    dim3 ggrid(3, (N_NODES + GM_BM - 1) / GM_BM);
    gemm_cat_kernel<<<ggrid, 256>>>(node_feat);

    // join + consume
    cudaStreamWaitEvent(0, evJoin, 0);
    fused_kernel<<<(N_NODES * 32 + 255) / 256, 256>>>(edge_feat, out);
}

// round 12
// speedup vs baseline: 1.0665x; 1.0547x over previous
#include <cuda_runtime.h>
#include <cuda_bf16.h>
#include <cuda_fp16.h>
#include <mma.h>
#include <math_constants.h>

using namespace nvcuda;

// Problem constants
#define N_NODES   50000
#define N_EDGES   800000
#define IN_FEATS  256
#define EDGE_FEATS 64
#define NUM_HEADS 4
#define OUT_FEATS 32
#define HF        128           // NUM_HEADS*OUT_FEATS
#define QCOLS     256           // NUM_HEADS*EDGE_FEATS
#define NCAT      384           // HF + QCOLS

#define SCAN_BLK  512
#define NB_SCAN   ((N_NODES + SCAN_BLK - 1) / SCAN_BLK)   // 98

#define GM_BM 128
#define GM_BK 32

// Scratch (static device globals; no allocation allowed)
__device__ __half g_wcat[IN_FEATS * NCAT];     // [W_node | W_node@Wbig*scale] fp16
__device__ __half g_hh[N_NODES * HF];          // projected node feats fp16
__device__ __half g_qh[N_NODES * QCOLS];       // q[n,h,k] fp16 (scale baked in)
__device__ int    g_cnt[N_NODES];
__device__ int    g_off[N_NODES + 1];
__device__ int    g_cur[N_NODES];
__device__ int2   g_es[N_EDGES];               // (eid, src) grouped by dst
__device__ int    g_part[NB_SCAN];
__device__ int    g_partx[NB_SCAN];

// ---------------------------------------------------------------------------
__global__ void zero_cnt_kernel() {
    int i = blockIdx.x * blockDim.x + threadIdx.x;
    if (i < N_NODES) g_cnt[i] = 0;
}

// ---------------------------------------------------------------------------
// Wcat precompute.
// ---------------------------------------------------------------------------
__global__ __launch_bounds__(NCAT) void wcat_kernel(
    const float* __restrict__ Wn, const float* __restrict__ We) {
    __shared__ float We_s[EDGE_FEATS * HF];   // 32KB
    __shared__ float wn_row[HF];

    const int c_in = blockIdx.x;
    const int j = threadIdx.x;

    for (int i = j; i < EDGE_FEATS * HF; i += NCAT) We_s[i] = We[i];
    if (j < HF) wn_row[j] = Wn[(size_t)c_in * HF + j];
    __syncthreads();

    float out;
    if (j < HF) {
        out = wn_row[j];
    } else {
        const int jj = j - HF;
        const int h = jj >> 6;
        const int k = jj & 63;
        float acc = 0.0f;
#pragma unroll
        for (int f = 0; f < OUT_FEATS; f++)
            acc += wn_row[h * OUT_FEATS + f] * We_s[k * HF + h * OUT_FEATS + f];
        out = acc * 0.17677669529663687f;   // 1/sqrt(32)
    }
    g_wcat[(size_t)c_in * NCAT + j] = __float2half_rn(out);
}

// ---------------------------------------------------------------------------
// Single fused GEMM: [h | q] = A[50000,256] @ Wcat[256,384], wmma fp16/fp32.
// Double-buffered smem mainloop; grid (3 n-tiles, 391 m-tiles) for A L2 reuse.
// ---------------------------------------------------------------------------
__global__ __launch_bounds__(256) void gemm_cat_kernel(const float* __restrict__ A) {
    __shared__ __half As[2][GM_BM][GM_BK + 8];
    __shared__ __half Ws[2][GM_BK][128 + 8];
    __shared__ float  patch[8][16 * 16];

    const int tid  = threadIdx.x;
    const int warp = tid >> 5;
    const int lane = tid & 31;
    const int wm   = warp >> 1;
    const int wn   = warp & 1;
    const int m0   = blockIdx.y * GM_BM;
    const int nbase = blockIdx.x * 128;

    const int ar = tid >> 3;
    const int ac = (tid & 7) * 4;
    const int wr = tid >> 4;
    const int wc = (tid & 15) * 8;

    wmma::fragment<wmma::accumulator, 16, 16, 16, float> c[2][4];
#pragma unroll
    for (int i = 0; i < 2; i++)
#pragma unroll
        for (int j = 0; j < 4; j++) wmma::fill_fragment(c[i][j], 0.0f);

    float4 areg[4];
    uint4  wreg[2];

#pragma unroll
    for (int i = 0; i < 4; i++) {
        int gr = m0 + ar + i * 32;
        areg[i] = make_float4(0.f, 0.f, 0.f, 0.f);
        if (gr < N_NODES) areg[i] = *(const float4*)&A[(size_t)gr * IN_FEATS + ac];
    }
#pragma unroll
    for (int i = 0; i < 2; i++)
        wreg[i] = *(const uint4*)&g_wcat[(size_t)(wr + i * 16) * NCAT + nbase + wc];

#pragma unroll
    for (int i = 0; i < 4; i++) {
        As[0][ar + i * 32][ac + 0] = __float2half_rn(areg[i].x);
        As[0][ar + i * 32][ac + 1] = __float2half_rn(areg[i].y);
        As[0][ar + i * 32][ac + 2] = __float2half_rn(areg[i].z);
        As[0][ar + i * 32][ac + 3] = __float2half_rn(areg[i].w);
    }
#pragma unroll
    for (int i = 0; i < 2; i++)
        *(uint4*)&Ws[0][wr + i * 16][wc] = wreg[i];
    __syncthreads();

    int buf = 0;
#pragma unroll
    for (int k0 = 0; k0 < IN_FEATS; k0 += GM_BK) {
        const bool has_next = (k0 + GM_BK < IN_FEATS);

        if (has_next) {
            const int kn = k0 + GM_BK;
#pragma unroll
            for (int i = 0; i < 4; i++) {
                int gr = m0 + ar + i * 32;
                areg[i] = make_float4(0.f, 0.f, 0.f, 0.f);
                if (gr < N_NODES) areg[i] = *(const float4*)&A[(size_t)gr * IN_FEATS + kn + ac];
            }
#pragma unroll
            for (int i = 0; i < 2; i++)
                wreg[i] = *(const uint4*)&g_wcat[(size_t)(kn + wr + i * 16) * NCAT + nbase + wc];
        }

#pragma unroll
        for (int kk = 0; kk < GM_BK; kk += 16) {
            wmma::fragment<wmma::matrix_a, 16, 16, 16, __half, wmma::row_major> a[2];
            wmma::fragment<wmma::matrix_b, 16, 16, 16, __half, wmma::row_major> b[4];
#pragma unroll
            for (int i = 0; i < 2; i++)
                wmma::load_matrix_sync(a[i], &As[buf][wm * 32 + i * 16][kk], GM_BK + 8);
#pragma unroll
            for (int j = 0; j < 4; j++)
                wmma::load_matrix_sync(b[j], &Ws[buf][kk][wn * 64 + j * 16], 128 + 8);
#pragma unroll
            for (int i = 0; i < 2; i++)
#pragma unroll
                for (int j = 0; j < 4; j++)
                    wmma::mma_sync(c[i][j], a[i], b[j], c[i][j]);
        }

        if (has_next) {
            const int nb = buf ^ 1;
#pragma unroll
            for (int i = 0; i < 4; i++) {
                As[nb][ar + i * 32][ac + 0] = __float2half_rn(areg[i].x);
                As[nb][ar + i * 32][ac + 1] = __float2half_rn(areg[i].y);
                As[nb][ar + i * 32][ac + 2] = __float2half_rn(areg[i].z);
                As[nb][ar + i * 32][ac + 3] = __float2half_rn(areg[i].w);
            }
#pragma unroll
            for (int i = 0; i < 2; i++)
                *(uint4*)&Ws[nb][wr + i * 16][wc] = wreg[i];
            __syncthreads();
            buf = nb;
        }
    }

    __syncthreads();
    const int prow = lane >> 1;
    const int pcol = (lane & 1) * 8;
#pragma unroll
    for (int i = 0; i < 2; i++) {
#pragma unroll
        for (int j = 0; j < 4; j++) {
            wmma::store_matrix_sync(patch[warp], c[i][j], 16, wmma::mem_row_major);
            __syncwarp();
            const int n = m0 + wm * 32 + i * 16 + prow;
            if (n < N_NODES) {
                const float* pr = patch[warp] + prow * 16 + pcol;
                union { uint4 u; __half2 h2[4]; } pack;
                pack.h2[0] = __floats2half2_rn(pr[0], pr[1]);
                pack.h2[1] = __floats2half2_rn(pr[2], pr[3]);
                pack.h2[2] = __floats2half2_rn(pr[4], pr[5]);
                pack.h2[3] = __floats2half2_rn(pr[6], pr[7]);
                const int C = nbase + wn * 64 + j * 16 + pcol;
                if (C < HF) {
                    *(uint4*)&g_hh[(size_t)n * HF + C] = pack.u;
                } else {
                    *(uint4*)&g_qh[(size_t)n * QCOLS + (C - HF)] = pack.u;
                }
            }
            __syncwarp();
        }
    }
}

// ---------------------------------------------------------------------------
// CSR build: histogram -> scan (3 kernels) -> scatter (packed int2)
// ---------------------------------------------------------------------------
__global__ void hist_kernel(const int* __restrict__ dst) {
    int e = blockIdx.x * blockDim.x + threadIdx.x;
    if (e < N_EDGES) atomicAdd(&g_cnt[dst[e]], 1);
}

__global__ __launch_bounds__(SCAN_BLK) void scan1_kernel() {
    __shared__ int sm[SCAN_BLK];
    int t = threadIdx.x;
    int i = blockIdx.x * SCAN_BLK + t;
    sm[t] = (i < N_NODES) ? g_cnt[i] : 0;
    __syncthreads();
    for (int off = SCAN_BLK / 2; off > 0; off >>= 1) {
        if (t < off) sm[t] += sm[t + off];
        __syncthreads();
    }
    if (t == 0) g_part[blockIdx.x] = sm[0];
}

__global__ __launch_bounds__(128) void scan2_kernel() {
    __shared__ int sm[2][128];
    int t = threadIdx.x;
    int v = (t < NB_SCAN) ? g_part[t] : 0;
    int pi = 0;
    sm[0][t] = v;
    __syncthreads();
#pragma unroll
    for (int off = 1; off < 128; off <<= 1) {
        int add = (t >= off) ? sm[pi][t - off] : 0;
        sm[pi ^ 1][t] = sm[pi][t] + add;
        pi ^= 1;
        __syncthreads();
    }
    if (t < NB_SCAN) g_partx[t] = sm[pi][t] - v;   // exclusive
}

__global__ __launch_bounds__(SCAN_BLK) void scan3_kernel() {
    __shared__ int sm[2][SCAN_BLK];
    int t = threadIdx.x;
    int i = blockIdx.x * SCAN_BLK + t;
    int v = (i < N_NODES) ? g_cnt[i] : 0;
    int pi = 0;
    sm[0][t] = v;
    __syncthreads();
#pragma unroll
    for (int off = 1; off < SCAN_BLK; off <<= 1) {
        int add = (t >= off) ? sm[pi][t - off] : 0;
        sm[pi ^ 1][t] = sm[pi][t] + add;
        pi ^= 1;
        __syncthreads();
    }
    if (i < N_NODES) {
        int excl = g_partx[blockIdx.x] + sm[pi][t] - v;
        g_off[i] = excl;
        g_cur[i] = excl;
    }
    if (blockIdx.x == 0 && t == 0) g_off[N_NODES] = N_EDGES;
}

__global__ void scatter_kernel(const int* __restrict__ src, const int* __restrict__ dst) {
    int e = blockIdx.x * blockDim.x + threadIdx.x;
    if (e < N_EDGES) {
        int pos = atomicAdd(&g_cur[dst[e]], 1);
        g_es[pos] = make_int2(e, src[e]);
    }
}

// ---------------------------------------------------------------------------
// Fused: warp per dst node, NO max subtraction. lane l: head h=l>>3,
// k-chunk k0=(l&7)*8. Prefetch distance 2 on the (eid,src) chain.
// ---------------------------------------------------------------------------
__global__ __launch_bounds__(256) void fused_kernel(
    const float* __restrict__ ef, float* __restrict__ out) {
    const int d = (blockIdx.x * 256 + threadIdx.x) >> 5;
    if (d >= N_NODES) return;
    const int lane = threadIdx.x & 31;
    const int h  = lane >> 3;
    const int k0 = (lane & 7) * 8;

    const int beg = __ldg(&g_off[d]);
    const int end = __ldg(&g_off[d + 1]);

    float den = 0.0f;
    float4 acc = make_float4(0.f, 0.f, 0.f, 0.f);

    if (beg < end) {
        const int last = end - 1;
        int2 e0 = __ldg(&g_es[beg]);
        int2 e1 = (beg < last) ? __ldg(&g_es[beg + 1]) : e0;

#pragma unroll 2
        for (int j = beg; j < end; j++) {
            const int eid_c = e0.x;
            const int s_c   = e0.y;
            e0 = e1;
            const int jn2 = (j + 2 < end) ? j + 2 : last;
            e1 = __ldg(&g_es[jn2]);

            const float4 ef0 = *(const float4*)(ef + (size_t)eid_c * EDGE_FEATS + k0);
            const float4 ef1 = *(const float4*)(ef + (size_t)eid_c * EDGE_FEATS + k0 + 4);

            const uint4 qv = *(const uint4*)(g_qh + (size_t)s_c * QCOLS + h * EDGE_FEATS + k0);
            const float2 q0 = __half22float2(*(const __half2*)&qv.x);
            const float2 q1 = __half22float2(*(((const __half2*)&qv.x) + 1));
            const float2 q2 = __half22float2(*(const __half2*)&qv.z);
            const float2 q3 = __half22float2(*(((const __half2*)&qv.z) + 1));

            float p = ef0.x * q0.x + ef0.y * q0.y + ef0.z * q1.x + ef0.w * q1.y
                    + ef1.x * q2.x + ef1.y * q2.y + ef1.z * q3.x + ef1.w * q3.y;
            p += __shfl_xor_sync(0xffffffffu, p, 1);
            p += __shfl_xor_sync(0xffffffffu, p, 2);
            p += __shfl_xor_sync(0xffffffffu, p, 4);

            const float sc = (p > 0.0f) ? p : 0.01f * p;   // leaky relu
            const float w  = __expf(sc);

            const uint2 hvu = *(const uint2*)(g_hh + (size_t)s_c * HF + lane * 4);
            const float2 h01 = __half22float2(*(const __half2*)&hvu.x);
            const float2 h23 = __half22float2(*(const __half2*)&hvu.y);

            den   += w;
            acc.x += w * h01.x;
            acc.y += w * h01.y;
            acc.z += w * h23.x;
            acc.w += w * h23.y;
        }
    }

    const float inv = (den > 0.0f) ? __frcp_rn(den) : 0.0f;
    float4 o = make_float4(acc.x * inv, acc.y * inv, acc.z * inv, acc.w * inv);
    *(float4*)(out + (size_t)d * HF + lane * 4) = o;
}

// ---------------------------------------------------------------------------
// True fork/join: NOTHING launches on the (legacy) default stream between
// fork and join — legacy-stream implicit sync was serializing the previous
// attempt inside capture. Branch A on sA, branch B on sB, join on default.
// ---------------------------------------------------------------------------
extern "C" void kernel_launch(void* const* d_in, const int* in_sizes, int n_in,
                              void* d_out, int out_size) {
    const float* node_feat = (const float*)d_in[0];
    const float* edge_feat = (const float*)d_in[1];
    const int*   src       = (const int*)d_in[2];
    const int*   dst       = (const int*)d_in[3];
    const float* W_node    = (const float*)d_in[4];
    const float* W_edge    = (const float*)d_in[5];
    float* out = (float*)d_out;

    static cudaStream_t sA = nullptr, sB = nullptr;
    static cudaEvent_t evFork = nullptr, evA = nullptr, evB = nullptr;
    if (sA == nullptr) {
        cudaStreamCreateWithFlags(&sA, cudaStreamNonBlocking);
        cudaStreamCreateWithFlags(&sB, cudaStreamNonBlocking);
        cudaEventCreateWithFlags(&evFork, cudaEventDisableTiming);
        cudaEventCreateWithFlags(&evA, cudaEventDisableTiming);
        cudaEventCreateWithFlags(&evB, cudaEventDisableTiming);
    }

    // fork from the capture-origin (default) stream
    cudaEventRecord(evFork, 0);
    cudaStreamWaitEvent(sA, evFork, 0);
    cudaStreamWaitEvent(sB, evFork, 0);

    // branch A: projection GEMM chain on sA
    wcat_kernel<<<IN_FEATS, NCAT, 0, sA>>>(W_node, W_edge);
    {
        dim3 ggrid(3, (N_NODES + GM_BM - 1) / GM_BM);
        gemm_cat_kernel<<<ggrid, 256, 0, sA>>>(node_feat);
    }
    cudaEventRecord(evA, sA);

    // branch B: CSR build on sB
    zero_cnt_kernel<<<(N_NODES + 255) / 256, 256, 0, sB>>>();
    hist_kernel<<<(N_EDGES + 255) / 256, 256, 0, sB>>>(dst);
    scan1_kernel<<<NB_SCAN, SCAN_BLK, 0, sB>>>();
    scan2_kernel<<<1, 128, 0, sB>>>();
    scan3_kernel<<<NB_SCAN, SCAN_BLK, 0, sB>>>();
    scatter_kernel<<<(N_EDGES + 255) / 256, 256, 0, sB>>>(src, dst);
    cudaEventRecord(evB, sB);

    // join on default stream, then consume both branches
    cudaStreamWaitEvent(0, evA, 0);
    cudaStreamWaitEvent(0, evB, 0);
    fused_kernel<<<(N_NODES * 32 + 255) / 256, 256>>>(edge_feat, out);
}